// round 7
// baseline (speedup 1.0000x reference)
#include <cuda_runtime.h>
#include <stdint.h>

// Voxel hash table, 2-level trilinear interpolation.
// 4 queries per warp; 8 lanes per query; each lane handles a float4 of features.
// Branchless gathers in batches of 4 (MLP=4); streaming loads/stores for the
// query + 128MB output streams keep the tables resident in L2.

#define TSIZE_MASK 0xFFFFFu        // TSIZE = 2^20
#define FDIM 32
#define QPW 4                      // queries per warp
#define LPQ 8                      // lanes per query (8 * float4 = 32 feats)

// PRIMES % TSIZE (exact int32 wraparound math, matches reference PM)
#define PM0 (73856093u % 1048576u)
#define PM1 (19349669u % 1048576u)
#define PM2 (83492791u % 1048576u)

struct LevelScalars {
    unsigned hx0, hx1, hy0, hy1, hz0, hz1;
    float fx, fy, fz;
};

__device__ __forceinline__ void level_prologue(float sx, float sy, float sz, LevelScalars& L)
{
    float bfx = floorf(sx), bfy = floorf(sy), bfz = floorf(sz);
    L.fx = sx - bfx; L.fy = sy - bfy; L.fz = sz - bfz;
    int bx = (int)bfx, by = (int)bfy, bz = (int)bfz;
    L.hx0 = (unsigned)bx * PM0; L.hx1 = L.hx0 + PM0;
    L.hy0 = (unsigned)by * PM1; L.hy1 = L.hy0 + PM1;
    L.hz0 = (unsigned)bz * PM2; L.hz1 = L.hz0 + PM2;
}

__device__ __forceinline__ void level_probe(const LevelScalars& L,
                                            const int* __restrict__ h2v, int v[8])
{
    unsigned xy00 = L.hx0 + L.hy0, xy01 = L.hx0 + L.hy1;
    unsigned xy10 = L.hx1 + L.hy0, xy11 = L.hx1 + L.hy1;
    v[0] = __ldg(h2v + ((xy00 + L.hz0) & TSIZE_MASK));
    v[1] = __ldg(h2v + ((xy00 + L.hz1) & TSIZE_MASK));
    v[2] = __ldg(h2v + ((xy01 + L.hz0) & TSIZE_MASK));
    v[3] = __ldg(h2v + ((xy01 + L.hz1) & TSIZE_MASK));
    v[4] = __ldg(h2v + ((xy10 + L.hz0) & TSIZE_MASK));
    v[5] = __ldg(h2v + ((xy10 + L.hz1) & TSIZE_MASK));
    v[6] = __ldg(h2v + ((xy11 + L.hz0) & TSIZE_MASK));
    v[7] = __ldg(h2v + ((xy11 + L.hz1) & TSIZE_MASK));
}

// Branchless gather: invalid corners load row 0 with weight 0 (exact zero
// contribution, matching the reference). Loads issued in batches of 4.
__device__ __forceinline__ void level_gather(const int v[8], const LevelScalars& L,
                                             const float* __restrict__ feats,
                                             int fcol, float4& out)
{
    float wx0 = 1.0f - L.fx, wx1 = L.fx;
    float wy0 = 1.0f - L.fy, wy1 = L.fy;
    float wz0 = 1.0f - L.fz, wz1 = L.fz;
    float wxy00 = wx0 * wy0, wxy01 = wx0 * wy1;
    float wxy10 = wx1 * wy0, wxy11 = wx1 * wy1;

    // corner c: bit2 -> x, bit1 -> y, bit0 -> z
    float w[8];
    w[0] = wxy00 * wz0; w[1] = wxy00 * wz1;
    w[2] = wxy01 * wz0; w[3] = wxy01 * wz1;
    w[4] = wxy10 * wz0; w[5] = wxy10 * wz1;
    w[6] = wxy11 * wz0; w[7] = wxy11 * wz1;

    const float4* base = (const float4*)(feats + fcol);
    float4 a = make_float4(0.f, 0.f, 0.f, 0.f);
    float4 b = make_float4(0.f, 0.f, 0.f, 0.f);

    #pragma unroll
    for (int g = 0; g < 2; g++) {           // two batches of 4 corners
        int   c0 = g * 4;
        // zero weight for invalid corners; clamp index so the load is safe
        float s0 = (v[c0+0] >= 0) ? w[c0+0] : 0.0f;
        float s1 = (v[c0+1] >= 0) ? w[c0+1] : 0.0f;
        float s2 = (v[c0+2] >= 0) ? w[c0+2] : 0.0f;
        float s3 = (v[c0+3] >= 0) ? w[c0+3] : 0.0f;
        int   i0 = max(v[c0+0], 0), i1 = max(v[c0+1], 0);
        int   i2 = max(v[c0+2], 0), i3 = max(v[c0+3], 0);

        // 4 independent 128B-coalesced loads in flight
        float4 f0 = __ldg(base + (size_t)i0 * (FDIM/4));
        float4 f1 = __ldg(base + (size_t)i1 * (FDIM/4));
        float4 f2 = __ldg(base + (size_t)i2 * (FDIM/4));
        float4 f3 = __ldg(base + (size_t)i3 * (FDIM/4));

        a.x = fmaf(s0, f0.x, a.x); a.y = fmaf(s0, f0.y, a.y);
        a.z = fmaf(s0, f0.z, a.z); a.w = fmaf(s0, f0.w, a.w);
        b.x = fmaf(s1, f1.x, b.x); b.y = fmaf(s1, f1.y, b.y);
        b.z = fmaf(s1, f1.z, b.z); b.w = fmaf(s1, f1.w, b.w);
        a.x = fmaf(s2, f2.x, a.x); a.y = fmaf(s2, f2.y, a.y);
        a.z = fmaf(s2, f2.z, a.z); a.w = fmaf(s2, f2.w, a.w);
        b.x = fmaf(s3, f3.x, b.x); b.y = fmaf(s3, f3.y, b.y);
        b.z = fmaf(s3, f3.z, b.z); b.w = fmaf(s3, f3.w, b.w);
    }
    out.x = a.x + b.x; out.y = a.y + b.y; out.z = a.z + b.z; out.w = a.w + b.w;
}

__global__ void __launch_bounds__(256, 6)
voxel_hash_kernel(const float* __restrict__ q,
                  const float* __restrict__ feats0,
                  const float* __restrict__ feats1,
                  const int*   __restrict__ h2v0,
                  const int*   __restrict__ h2v1,
                  float4* __restrict__ out4,
                  int M)
{
    int gtid  = blockIdx.x * blockDim.x + threadIdx.x;
    int lane  = gtid & 31;
    int warp  = gtid >> 5;
    int qsub  = lane >> 3;            // which of the 4 queries in this warp
    int flane = lane & 7;             // feature-quad index within the query
    int qidx  = warp * QPW + qsub;
    if (qidx >= M) return;

    // Streaming loads: query points are read exactly once — don't pollute L2.
    float qx = __ldcs(q + (size_t)qidx * 3 + 0);
    float qy = __ldcs(q + (size_t)qidx * 3 + 1);
    float qz = __ldcs(q + (size_t)qidx * 3 + 2);

    // Level 0: IEEE division (bit-match). Level 1: q/0.24 == (q/0.12)*0.5 exactly
    // (f32(0.24) is exactly 2*f32(0.12); scaling by 2 commutes with rn-division).
    float sx0 = __fdiv_rn(qx, 0.12f);
    float sy0 = __fdiv_rn(qy, 0.12f);
    float sz0 = __fdiv_rn(qz, 0.12f);

    LevelScalars L0, L1;
    level_prologue(sx0, sy0, sz0, L0);
    level_prologue(sx0 * 0.5f, sy0 * 0.5f, sz0 * 0.5f, L1);

    // Issue all 16 hash-table probes up front (MLP=16).
    int v0[8], v1[8];
    level_probe(L0, h2v0, v0);
    level_probe(L1, h2v1, v1);

    int fcol = flane * 4;
    float4 r0, r1;
    level_gather(v0, L0, feats0, fcol, r0);
    level_gather(v1, L1, feats1, fcol, r1);

    // Streaming stores: the 128MB output must not evict the L2-resident tables.
    size_t obase = (size_t)qidx * 16 + flane;
    __stcs(out4 + obase,     r0);
    __stcs(out4 + obase + 8, r1);
}

extern "C" void kernel_launch(void* const* d_in, const int* in_sizes, int n_in,
                              void* d_out, int out_size)
{
    const float* q      = (const float*)d_in[0];
    const float* feats0 = (const float*)d_in[1];
    const float* feats1 = (const float*)d_in[2];
    const int*   h2v0   = (const int*)d_in[3];
    const int*   h2v1   = (const int*)d_in[4];
    float4* out = (float4*)d_out;

    int M = in_sizes[0] / 3;
    int threads = 256;
    long long total = (long long)M * LPQ;     // 8 lanes per query
    int blocks = (int)((total + threads - 1) / threads);
    voxel_hash_kernel<<<blocks, threads>>>(q, feats0, feats1, h2v0, h2v1, out, M);
}